// round 6
// baseline (speedup 1.0000x reference)
#include <cuda_runtime.h>
#include <cuda_bf16.h>
#include <cstdint>
#include <math.h>

// Problem dims (fixed by setup_inputs)
#define B_ 256
#define D_ 2048
#define H_ 2048
#define K_ 64
#define T_ 32
#define G_ 8192           // 4*H
#define NS 32             // split-K factor for the fe GEMM
#define KC (H_ / NS)      // 64

// ---------------------------------------------------------------------------
// Scratch (device globals; no runtime allocation allowed)
// Weight rows stored GATE-INTERLEAVED: perm row p <- orig row (p&3)*H + (p>>2)
// ---------------------------------------------------------------------------
__device__ __nv_bfloat16 d_wih_hi[G_ * D_];
__device__ __nv_bfloat16 d_wih_lo[G_ * D_];
__device__ __nv_bfloat16 d_whh_hi[G_ * H_];
__device__ __nv_bfloat16 d_whh_lo[G_ * H_];
__device__ __nv_bfloat16 d_x_hi[B_ * D_];
__device__ __nv_bfloat16 d_x_lo[B_ * D_];
__device__ __nv_bfloat16 d_h_hi[B_ * H_];
__device__ __nv_bfloat16 d_h_lo[B_ * H_];
__device__ float d_bias[G_];               // permuted b_ih + b_hh
__device__ float d_xg[B_ * G_];            // permuted cols
__device__ float d_h [B_ * H_];
__device__ float d_c [B_ * H_];
__device__ float d_fep[NS * B_ * 2 * K_];

__device__ __forceinline__ uint32_t smem_to_u32(const void* p) {
    uint32_t a;
    asm("{ .reg .u64 t; cvta.to.shared.u64 t, %1; cvt.u32.u64 %0, t; }"
        : "=r"(a) : "l"(p));
    return a;
}

// mma.sync m16n8k16 bf16 -> fp32 accumulate (plain sm_80+ PTX)
#define MMA16816(c, a0, a1, a2, a3, b0, b1) \
    asm volatile( \
        "mma.sync.aligned.m16n8k16.row.col.f32.bf16.bf16.f32 " \
        "{%0,%1,%2,%3}, {%4,%5,%6,%7}, {%8,%9}, {%0,%1,%2,%3};" \
        : "+f"((c)[0]), "+f"((c)[1]), "+f"((c)[2]), "+f"((c)[3]) \
        : "r"(a0), "r"(a1), "r"(a2), "r"(a3), "r"(b0), "r"(b1))

#define LDSM4(r, addr) \
    asm volatile("ldmatrix.sync.aligned.m8n8.x4.shared.b16 {%0,%1,%2,%3}, [%4];" \
        : "=r"((r)[0]), "=r"((r)[1]), "=r"((r)[2]), "=r"((r)[3]) : "r"(addr))

// ---------------------------------------------------------------------------
// Tensor-core split-bf16 GEMM (Xhi*Whi + Xhi*Wlo + Xlo*Whi, fp32 accum),
// CTA tile 128m x 128n, BK=32, 8 warps (32m x 64n each),
// 5-stage cp.async pipeline (4 chunks in flight -> 128KB/SM outstanding).
// gate_mode=0: C[m,n] = acc + bias[n]                     (xg GEMM)
// gate_mode=1: g = acc + xg[m,n]; fused LSTM cell update   (recurrent GEMM)
// ---------------------------------------------------------------------------
#define BK    32
#define NCH   (D_ / BK)        // 64 chunks
#define ROWB  80               // padded row pitch (32 bf16 = 64B data + 16 pad)
#define TILEB (128 * ROWB)     // 10240
#define STAGEB (4 * TILEB)     // 40960
#define NSTAGE 5
#define SMEM_TOTAL (NSTAGE * STAGEB)   // 204800

__global__ __launch_bounds__(256, 1)
void gemm_mma2(const __nv_bfloat16* __restrict__ Xhi,
               const __nv_bfloat16* __restrict__ Xlo,
               const __nv_bfloat16* __restrict__ Whi,
               const __nv_bfloat16* __restrict__ Wlo,
               const float* __restrict__ xg,     // gate_mode=1
               const float* __restrict__ bias,   // gate_mode=0
               float* __restrict__ C,            // gate_mode=0
               float* __restrict__ h,
               float* __restrict__ c,
               __nv_bfloat16* __restrict__ hhi,
               __nv_bfloat16* __restrict__ hlo,
               int gate_mode)
{
    extern __shared__ __align__(16) char smem[];
    const uint32_t sm0 = smem_to_u32(smem);

    const int tid  = threadIdx.x;
    const int lane = tid & 31;
    const int w    = tid >> 5;
    const int wy   = w & 3;          // m sub-tile (4 x 32)
    const int wx   = w >> 2;         // n sub-tile (2 x 64)
    const int q    = lane & 3;
    const int g    = lane >> 2;
    const int bn   = blockIdx.x * 128;
    const int bm   = blockIdx.y * 128;

    const __nv_bfloat16* srcs[4] = {
        Xhi + (size_t)bm * D_, Xlo + (size_t)bm * D_,
        Whi + (size_t)bn * D_, Wlo + (size_t)bn * D_
    };

    // ldmatrix per-lane addressing
    const int lrow = (lane & 7) + ((lane >> 3) & 1) * 8;
    const int colh = (lane >> 4) * 16;

    float acc[2][8][4];
    #pragma unroll
    for (int a = 0; a < 2; a++)
        #pragma unroll
        for (int b = 0; b < 8; b++)
            #pragma unroll
            for (int d = 0; d < 4; d++) acc[a][b][d] = 0.f;

#define ISSUE(ch, st) do {                                                    \
    const int _kof = (ch) * BK;                                               \
    _Pragma("unroll")                                                         \
    for (int i = 0; i < 8; i++) {                                             \
        const int _idx = i * 256 + tid;                                       \
        const int _v   = _idx >> 9;                                           \
        const int _rem = _idx & 511;                                          \
        const int _row = _rem >> 2;                                           \
        const int _qu  = _rem & 3;                                            \
        uint32_t _dst = sm0 + (st) * STAGEB + _v * TILEB + _row * ROWB + _qu * 16; \
        const __nv_bfloat16* _sp = srcs[_v] + (size_t)_row * D_ + _kof + _qu * 8;  \
        asm volatile("cp.async.cg.shared.global [%0], [%1], 16;"              \
                     :: "r"(_dst), "l"(_sp));                                 \
    }                                                                         \
    asm volatile("cp.async.commit_group;" ::: "memory");                      \
} while (0)

    ISSUE(0, 0);
    ISSUE(1, 1);
    ISSUE(2, 2);
    ISSUE(3, 3);

    int st = 0;
    for (int ch = 0; ch < NCH; ch++) {
        // Ensure chunk ch has arrived: allowed pending = #groups issued after ch
        const int rem = NCH - 1 - ch;
        if (rem >= 3)      asm volatile("cp.async.wait_group 3;" ::: "memory");
        else if (rem == 2) asm volatile("cp.async.wait_group 2;" ::: "memory");
        else if (rem == 1) asm volatile("cp.async.wait_group 1;" ::: "memory");
        else               asm volatile("cp.async.wait_group 0;" ::: "memory");
        __syncthreads();
        {
            int nst = st + 4; if (nst >= NSTAGE) nst -= NSTAGE;
            if (ch + 4 < NCH) ISSUE(ch + 4, nst);
        }

        const uint32_t stb = sm0 + st * STAGEB;
        const uint32_t aHi = stb + (wy * 32 + lrow) * ROWB + colh;
        const uint32_t bHi = stb + 2 * TILEB + (wx * 64 + lrow) * ROWB + colh;

        #pragma unroll
        for (int ks = 0; ks < 2; ks++) {
            // Load ALL fragments for this k16 step first
            uint32_t ah[2][4], al[2][4], bh[4][4], bl[4][4];
            #pragma unroll
            for (int mb = 0; mb < 2; mb++) {
                LDSM4(ah[mb], aHi + mb * 16 * ROWB + ks * 32);
                LDSM4(al[mb], aHi + TILEB + mb * 16 * ROWB + ks * 32);
            }
            #pragma unroll
            for (int jj = 0; jj < 4; jj++) {
                LDSM4(bh[jj], bHi + jj * 16 * ROWB + ks * 32);
                LDSM4(bl[jj], bHi + TILEB + jj * 16 * ROWB + ks * 32);
            }
            // Term-major issue: 16 independent MMAs per term
            #pragma unroll
            for (int jj = 0; jj < 4; jj++)
                #pragma unroll
                for (int mb = 0; mb < 2; mb++) {
                    MMA16816(acc[mb][jj * 2],     ah[mb][0], ah[mb][1], ah[mb][2], ah[mb][3], bh[jj][0], bh[jj][2]);
                    MMA16816(acc[mb][jj * 2 + 1], ah[mb][0], ah[mb][1], ah[mb][2], ah[mb][3], bh[jj][1], bh[jj][3]);
                }
            #pragma unroll
            for (int jj = 0; jj < 4; jj++)
                #pragma unroll
                for (int mb = 0; mb < 2; mb++) {
                    MMA16816(acc[mb][jj * 2],     ah[mb][0], ah[mb][1], ah[mb][2], ah[mb][3], bl[jj][0], bl[jj][2]);
                    MMA16816(acc[mb][jj * 2 + 1], ah[mb][0], ah[mb][1], ah[mb][2], ah[mb][3], bl[jj][1], bl[jj][3]);
                }
            #pragma unroll
            for (int jj = 0; jj < 4; jj++)
                #pragma unroll
                for (int mb = 0; mb < 2; mb++) {
                    MMA16816(acc[mb][jj * 2],     al[mb][0], al[mb][1], al[mb][2], al[mb][3], bh[jj][0], bh[jj][2]);
                    MMA16816(acc[mb][jj * 2 + 1], al[mb][0], al[mb][1], al[mb][2], al[mb][3], bh[jj][1], bh[jj][3]);
                }
        }
        st = st + 1 >= NSTAGE ? 0 : st + 1;
        // next iteration's __syncthreads protects stage reuse
    }
#undef ISSUE

    // Epilogue
    if (gate_mode == 0) {
        #pragma unroll
        for (int mb = 0; mb < 2; mb++) {
            const int m0 = bm + wy * 32 + mb * 16 + g;
            #pragma unroll
            for (int j = 0; j < 8; j++) {
                const int n0 = bn + wx * 64 + j * 8 + 2 * q;
                const float d0 = bias[n0], d1 = bias[n0 + 1];
                *(float2*)(C + (size_t)m0 * G_ + n0) =
                    make_float2(acc[mb][j][0] + d0, acc[mb][j][1] + d1);
                *(float2*)(C + (size_t)(m0 + 8) * G_ + n0) =
                    make_float2(acc[mb][j][2] + d0, acc[mb][j][3] + d1);
            }
        }
        return;
    }

    // gate_mode == 1: fused LSTM cell update
    const int evn = (lane & 1) == 0;   // q even: holds (i,f); q odd: (g,o)
    #pragma unroll
    for (int mb = 0; mb < 2; mb++) {
        const int r0 = bm + wy * 32 + mb * 16 + g;
        #pragma unroll
        for (int j = 0; j < 8; j++) {
            const int n0 = bn + wx * 64 + j * 8 + 2 * q;
            const float2 p0 = *(const float2*)(xg + (size_t)r0 * G_ + n0);
            const float2 p1 = *(const float2*)(xg + (size_t)(r0 + 8) * G_ + n0);
            float v0 = acc[mb][j][0] + p0.x;
            float v1 = acc[mb][j][1] + p0.y;
            float v2 = acc[mb][j][2] + p1.x;
            float v3 = acc[mb][j][3] + p1.y;

            const float s0 = __shfl_xor_sync(0xffffffffu, v0, 1);
            const float s1 = __shfl_xor_sync(0xffffffffu, v1, 1);
            const float s2 = __shfl_xor_sync(0xffffffffu, v2, 1);
            const float s3 = __shfl_xor_sync(0xffffffffu, v3, 1);

            // even lane handles row r0; odd lane handles row r0+8
            const int   row = evn ? r0 : r0 + 8;
            const float gi = evn ? v0 : s2;
            const float gf = evn ? v1 : s3;
            const float gg = evn ? s0 : v2;
            const float go = evn ? s1 : v3;

            const float iv = 1.f / (1.f + expf(-gi));
            const float fv = 1.f / (1.f + expf(-gf));
            const float gv = tanhf(gg);
            const float ov = 1.f / (1.f + expf(-go));

            const int  u   = (n0 >> 2);               // original hidden unit
            const int  idx = row * H_ + u;
            const float cn = fv * c[idx] + iv * gv;
            c[idx] = cn;
            const float hv = ov * tanhf(cn);
            h[idx] = hv;
            const __nv_bfloat16 hb = __float2bfloat16(hv);
            hhi[idx] = hb;
            hlo[idx] = __float2bfloat16(hv - __bfloat162float(hb));
        }
    }
}

// ---------------------------------------------------------------------------
// Weight decomposition with gate-interleave permutation:
// out row p <- in row (p&3)*H + (p>>2)
// ---------------------------------------------------------------------------
__global__ void decomp_w(const float* __restrict__ src,
                         __nv_bfloat16* __restrict__ hi,
                         __nv_bfloat16* __restrict__ lo,
                         int kdim)
{
    const int i = blockIdx.x * blockDim.x + threadIdx.x;
    if (i >= G_ * D_) return;
    const int p   = i / kdim;
    const int col = i - p * kdim;
    const int srow = (p & 3) * H_ + (p >> 2);
    const float v = src[(size_t)srow * kdim + col];
    const __nv_bfloat16 hb = __float2bfloat16(v);
    hi[i] = hb;
    lo[i] = __float2bfloat16(v - __bfloat162float(hb));
}

__global__ void decomp_kernel(const float* __restrict__ src,
                              __nv_bfloat16* __restrict__ hi,
                              __nv_bfloat16* __restrict__ lo,
                              int n)
{
    const int i = blockIdx.x * blockDim.x + threadIdx.x;
    if (i >= n) return;
    const float v = src[i];
    const __nv_bfloat16 hb = __float2bfloat16(v);
    hi[i] = hb;
    lo[i] = __float2bfloat16(v - __bfloat162float(hb));
}

__global__ void bias_comb(const float* __restrict__ bih,
                          const float* __restrict__ bhh,
                          float* __restrict__ bias)
{
    const int p = blockIdx.x * blockDim.x + threadIdx.x;
    if (p >= G_) return;
    const int o = (p & 3) * H_ + (p >> 2);
    bias[p] = bih[o] + bhh[o];
}

// ---------------------------------------------------------------------------
// t=0 gate: g = xg (h0 = 0), permuted layout
// ---------------------------------------------------------------------------
__global__ void gate0_kernel(const float* __restrict__ xg,
                             float* __restrict__ h,
                             float* __restrict__ c,
                             __nv_bfloat16* __restrict__ hhi,
                             __nv_bfloat16* __restrict__ hlo)
{
    const int idx = blockIdx.x * blockDim.x + threadIdx.x;
    if (idx >= B_ * H_) return;
    const int b = idx / H_;
    const int u = idx - b * H_;
    const float* gr = xg + (size_t)b * G_ + 4 * u;

    const float iv = 1.f / (1.f + expf(-gr[0]));
    const float gv = tanhf(gr[2]);
    const float ov = 1.f / (1.f + expf(-gr[3]));

    const float cn = iv * gv;          // c0 = 0
    c[idx] = cn;
    const float hv = ov * tanhf(cn);
    h[idx] = hv;
    const __nv_bfloat16 hb = __float2bfloat16(hv);
    hhi[idx] = hb;
    hlo[idx] = __float2bfloat16(hv - __bfloat162float(hb));
}

// ---------------------------------------------------------------------------
// fe GEMM, split-K: part[s][m][n] = sum_{k in chunk s} h[m,k] * W_fe[n,k]
// ---------------------------------------------------------------------------
__global__ __launch_bounds__(256, 1)
void gemm_fe(const float* __restrict__ hmat,
             const float* __restrict__ Wfe,
             float* __restrict__ part)
{
    __shared__ float As[16][68];
    __shared__ float Bs[16][132];

    const int ks   = blockIdx.x;
    const int bm   = blockIdx.y * 64;
    const int koff = ks * KC;
    const int tid  = threadIdx.x;
    const int tx   = tid & 31;
    const int ty   = tid >> 5;

    float acc[8][4];
    #pragma unroll
    for (int i = 0; i < 8; i++)
        #pragma unroll
        for (int j = 0; j < 4; j++) acc[i][j] = 0.f;

    for (int k0 = 0; k0 < KC; k0 += 16) {
        {
            const int row = tid >> 2;
            const int c4  = (tid & 3) * 4;
            float4 v = *(const float4*)(hmat + (size_t)(bm + row) * H_ + koff + k0 + c4);
            As[c4 + 0][row] = v.x;  As[c4 + 1][row] = v.y;
            As[c4 + 2][row] = v.z;  As[c4 + 3][row] = v.w;
        }
        #pragma unroll
        for (int r = 0; r < 2; r++) {
            const int idx = tid + r * 256;
            const int rowb = idx >> 2;
            const int c4  = (idx & 3) * 4;
            float4 v = *(const float4*)(Wfe + (size_t)rowb * H_ + koff + k0 + c4);
            Bs[c4 + 0][rowb] = v.x;  Bs[c4 + 1][rowb] = v.y;
            Bs[c4 + 2][rowb] = v.z;  Bs[c4 + 3][rowb] = v.w;
        }
        __syncthreads();

        #pragma unroll
        for (int kk = 0; kk < 16; kk++) {
            float a[8], b[4];
            #pragma unroll
            for (int i = 0; i < 8; i++) a[i] = As[kk][ty + i * 8];
            #pragma unroll
            for (int j = 0; j < 4; j++) b[j] = Bs[kk][tx + j * 32];
            #pragma unroll
            for (int i = 0; i < 8; i++)
                #pragma unroll
                for (int j = 0; j < 4; j++)
                    acc[i][j] = fmaf(a[i], b[j], acc[i][j]);
        }
        __syncthreads();
    }

    #pragma unroll
    for (int i = 0; i < 8; i++) {
        const int m = bm + ty + i * 8;
        #pragma unroll
        for (int j = 0; j < 4; j++) {
            const int n = tx + j * 32;
            part[((size_t)ks * B_ + m) * (2 * K_) + n] = acc[i][j];
        }
    }
}

// ---------------------------------------------------------------------------
// z epilogue
// ---------------------------------------------------------------------------
__global__ void z_kernel(const float* __restrict__ eps,
                         const float* __restrict__ bfe,
                         const float* __restrict__ part,
                         float* __restrict__ out,
                         int t)
{
    const int idx = blockIdx.x * blockDim.x + threadIdx.x;
    if (idx >= B_ * K_) return;
    const int b = idx / K_;
    const int k = idx - b * K_;

    float mu = bfe[k];
    float sr = bfe[k + K_];
    #pragma unroll
    for (int s = 0; s < NS; s++) {
        const float* p = part + ((size_t)s * B_ + b) * (2 * K_);
        mu += p[k];
        sr += p[k + K_];
    }

    const float xv  = sr - 5.f;
    const float sig = (xv > 20.f) ? xv : log1pf(expf(xv));
    const float e   = eps[((size_t)t * B_ + b) * K_ + k];
    const float z   = e * sig + mu;

    const size_t plane = (size_t)B_ * K_ * T_;
    const size_t o = ((size_t)b * K_ + k) * T_ + t;
    out[o]             = z;
    out[o + plane]     = mu;
    out[o + 2 * plane] = sig;
}

__global__ void hc_copy(const float* __restrict__ h,
                        const float* __restrict__ c,
                        float* __restrict__ out)
{
    const int idx = blockIdx.x * blockDim.x + threadIdx.x;
    if (idx >= B_ * H_) return;
    const size_t base = 3 * (size_t)B_ * K_ * T_;
    out[base + idx]           = h[idx];
    out[base + B_ * H_ + idx] = c[idx];
}

// ---------------------------------------------------------------------------
extern "C" void kernel_launch(void* const* d_in, const int* in_sizes, int n_in,
                              void* d_out, int out_size)
{
    const float* x   = (const float*)d_in[0];
    const float* eps = (const float*)d_in[1];
    const float* Wih = (const float*)d_in[2];
    const float* Whh = (const float*)d_in[3];
    const float* bih = (const float*)d_in[4];
    const float* bhh = (const float*)d_in[5];
    const float* Wfe = (const float*)d_in[6];
    const float* bfe = (const float*)d_in[7];
    float* out = (float*)d_out;

    __nv_bfloat16 *wih_hi, *wih_lo, *whh_hi, *whh_lo, *x_hi, *x_lo, *h_hi, *h_lo;
    float *xg, *h, *c, *fep, *bias;
    cudaGetSymbolAddress((void**)&wih_hi, d_wih_hi);
    cudaGetSymbolAddress((void**)&wih_lo, d_wih_lo);
    cudaGetSymbolAddress((void**)&whh_hi, d_whh_hi);
    cudaGetSymbolAddress((void**)&whh_lo, d_whh_lo);
    cudaGetSymbolAddress((void**)&x_hi,   d_x_hi);
    cudaGetSymbolAddress((void**)&x_lo,   d_x_lo);
    cudaGetSymbolAddress((void**)&h_hi,   d_h_hi);
    cudaGetSymbolAddress((void**)&h_lo,   d_h_lo);
    cudaGetSymbolAddress((void**)&xg,   d_xg);
    cudaGetSymbolAddress((void**)&h,    d_h);
    cudaGetSymbolAddress((void**)&c,    d_c);
    cudaGetSymbolAddress((void**)&fep,  d_fep);
    cudaGetSymbolAddress((void**)&bias, d_bias);

    cudaFuncSetAttribute(gemm_mma2, cudaFuncAttributeMaxDynamicSharedMemorySize,
                         SMEM_TOTAL);

    const dim3 gTc(G_ / 128, B_ / 128);    // (64, 2)
    const dim3 gFe(NS, B_ / 64);           // (32, 4)
    const int  eltBlocks = (B_ * H_ + 255) / 256;
    const int  zBlocks   = (B_ * K_ + 255) / 256;

    // Prep: permuted weight decomposition + bias combine + x decomposition
    decomp_w<<<(G_ * D_ + 255) / 256, 256>>>(Wih, wih_hi, wih_lo, D_);
    decomp_w<<<(G_ * H_ + 255) / 256, 256>>>(Whh, whh_hi, whh_lo, H_);
    decomp_kernel<<<(B_ * D_ + 255) / 256, 256>>>(x, x_hi, x_lo, B_ * D_);
    bias_comb<<<(G_ + 255) / 256, 256>>>(bih, bhh, bias);

    // xg = x @ Wih_perm^T + bias_perm   (permuted cols)
    gemm_mma2<<<gTc, 256, SMEM_TOTAL>>>(x_hi, x_lo, wih_hi, wih_lo,
                                        nullptr, bias, xg,
                                        nullptr, nullptr, nullptr, nullptr, 0);

    for (int t = 0; t < T_; t++) {
        if (t == 0) {
            gate0_kernel<<<eltBlocks, 256>>>(xg, h, c, h_hi, h_lo);
        } else {
            gemm_mma2<<<gTc, 256, SMEM_TOTAL>>>(h_hi, h_lo, whh_hi, whh_lo,
                                                xg, nullptr, nullptr,
                                                h, c, h_hi, h_lo, 1);
        }
        gemm_fe<<<gFe, 256>>>(h, Wfe, fep);
        z_kernel<<<zBlocks, 256>>>(eps, bfe, fep, out, t);
    }

    hc_copy<<<eltBlocks, 256>>>(h, c, out);
}

// round 8
// speedup vs baseline: 1.0733x; 1.0733x over previous
#include <cuda_runtime.h>
#include <cuda_bf16.h>
#include <cstdint>
#include <math.h>

// Problem dims (fixed by setup_inputs)
#define B_ 256
#define D_ 2048
#define H_ 2048
#define K_ 64
#define T_ 32
#define G_ 8192           // 4*H
#define NS 32             // split-K factor for the fe GEMM
#define KC (H_ / NS)      // 64

// ---------------------------------------------------------------------------
// Scratch (device globals; no runtime allocation allowed)
// Weight rows stored GATE-INTERLEAVED: perm row p <- orig row (p&3)*H + (p>>2)
// h_hi/h_lo are PING-PONG buffered across ticks (WAR-race fix).
// ---------------------------------------------------------------------------
__device__ __nv_bfloat16 d_wih_hi[G_ * D_];
__device__ __nv_bfloat16 d_wih_lo[G_ * D_];
__device__ __nv_bfloat16 d_whh_hi[G_ * H_];
__device__ __nv_bfloat16 d_whh_lo[G_ * H_];
__device__ __nv_bfloat16 d_x_hi[B_ * D_];
__device__ __nv_bfloat16 d_x_lo[B_ * D_];
__device__ __nv_bfloat16 d_h_hi[2][B_ * H_];
__device__ __nv_bfloat16 d_h_lo[2][B_ * H_];
__device__ float d_bias[G_];               // permuted b_ih + b_hh
__device__ float d_xg[B_ * G_];            // permuted cols
__device__ float d_h [B_ * H_];
__device__ float d_c [B_ * H_];
__device__ float d_fep[NS * B_ * 2 * K_];

__device__ __forceinline__ uint32_t smem_to_u32(const void* p) {
    uint32_t a;
    asm("{ .reg .u64 t; cvta.to.shared.u64 t, %1; cvt.u32.u64 %0, t; }"
        : "=r"(a) : "l"(p));
    return a;
}

// mma.sync m16n8k16 bf16 -> fp32 accumulate (plain sm_80+ PTX)
#define MMA16816(c, a0, a1, a2, a3, b0, b1) \
    asm volatile( \
        "mma.sync.aligned.m16n8k16.row.col.f32.bf16.bf16.f32 " \
        "{%0,%1,%2,%3}, {%4,%5,%6,%7}, {%8,%9}, {%0,%1,%2,%3};" \
        : "+f"((c)[0]), "+f"((c)[1]), "+f"((c)[2]), "+f"((c)[3]) \
        : "r"(a0), "r"(a1), "r"(a2), "r"(a3), "r"(b0), "r"(b1))

#define LDSM4(r, addr) \
    asm volatile("ldmatrix.sync.aligned.m8n8.x4.shared.b16 {%0,%1,%2,%3}, [%4];" \
        : "=r"((r)[0]), "=r"((r)[1]), "=r"((r)[2]), "=r"((r)[3]) : "r"(addr))

// ---------------------------------------------------------------------------
// Tensor-core split-bf16 GEMM (Xhi*Whi + Xhi*Wlo + Xlo*Whi, fp32 accum)
// CTA tile 64m x 128n, BK=32, 8 warps (warp = 32m x 32n), 3-stage cp.async.
// grid (64 n-tiles, 4 m-tiles) = 256 CTAs -> 2 CTAs/SM (smem 90KB each).
// gate_mode=0: C[m,n] = acc + bias[n]                     (xg GEMM)
// gate_mode=1: g = acc + xg[m,n]; fused LSTM cell update   (recurrent GEMM)
//   X operand (hhi_in/hlo_in) and epilogue output (hhi_out/hlo_out) are
//   DIFFERENT buffers (ping-pong) -> no WAR race across CTAs.
// ---------------------------------------------------------------------------
#define BK     32
#define NCH    (D_ / BK)       // 64 chunks
#define ROWB   80              // padded row pitch (32 bf16 = 64B data + 16 pad)
#define TILEA  (64 * ROWB)     // 5120  (X tile: 64 rows)
#define TILEW  (128 * ROWB)    // 10240 (W tile: 128 rows)
#define OFF_XHI 0
#define OFF_XLO TILEA
#define OFF_WHI (2 * TILEA)
#define OFF_WLO (2 * TILEA + TILEW)
#define STAGEB  (2 * TILEA + 2 * TILEW)   // 30720
#define NSTAGE  3
#define SMEM_TOTAL (NSTAGE * STAGEB)      // 92160

__global__ __launch_bounds__(256, 2)
void gemm_mma2(const __nv_bfloat16* __restrict__ Xhi,
               const __nv_bfloat16* __restrict__ Xlo,
               const __nv_bfloat16* __restrict__ Whi,
               const __nv_bfloat16* __restrict__ Wlo,
               const float* __restrict__ xg,     // gate_mode=1
               const float* __restrict__ bias,   // gate_mode=0
               float* __restrict__ C,            // gate_mode=0
               float* __restrict__ h,
               float* __restrict__ c,
               __nv_bfloat16* __restrict__ hhi_out,
               __nv_bfloat16* __restrict__ hlo_out,
               int gate_mode)
{
    extern __shared__ __align__(16) char smem[];
    const uint32_t sm0 = smem_to_u32(smem);

    const int tid  = threadIdx.x;
    const int lane = tid & 31;
    const int w    = tid >> 5;
    const int wy   = w & 1;          // m sub-tile (2 x 32)
    const int wx   = w >> 1;         // n sub-tile (4 x 32)
    const int q    = lane & 3;
    const int g    = lane >> 2;
    const int bn   = blockIdx.x * 128;
    const int bm   = blockIdx.y * 64;

    const __nv_bfloat16* xsrc[2] = { Xhi + (size_t)bm * D_, Xlo + (size_t)bm * D_ };
    const __nv_bfloat16* wsrc[2] = { Whi + (size_t)bn * D_, Wlo + (size_t)bn * D_ };

    // ldmatrix per-lane addressing
    const int lrow = (lane & 7) + ((lane >> 3) & 1) * 8;
    const int colh = (lane >> 4) * 16;

    float acc[2][4][4];
    #pragma unroll
    for (int a = 0; a < 2; a++)
        #pragma unroll
        for (int b = 0; b < 4; b++)
            #pragma unroll
            for (int d = 0; d < 4; d++) acc[a][b][d] = 0.f;

    // 1536 16B-loads per stage: [0,512) X tiles (hi,lo), [512,1536) W tiles
#define ISSUE(ch, st) do {                                                    \
    const int _kof = (ch) * BK;                                               \
    _Pragma("unroll")                                                         \
    for (int i = 0; i < 6; i++) {                                             \
        const int _idx = i * 256 + tid;                                       \
        uint32_t _dst; const __nv_bfloat16* _sp;                              \
        if (_idx < 512) {                                                     \
            const int _v = _idx >> 8, _rem = _idx & 255;                      \
            const int _row = _rem >> 2, _qu = _rem & 3;                       \
            _dst = sm0 + (st) * STAGEB + OFF_XHI + _v * TILEA + _row * ROWB + _qu * 16; \
            _sp  = xsrc[_v] + (size_t)_row * D_ + _kof + _qu * 8;             \
        } else {                                                              \
            const int _j = _idx - 512;                                        \
            const int _v = _j >> 9, _rem = _j & 511;                          \
            const int _row = _rem >> 2, _qu = _rem & 3;                       \
            _dst = sm0 + (st) * STAGEB + OFF_WHI + _v * TILEW + _row * ROWB + _qu * 16; \
            _sp  = wsrc[_v] + (size_t)_row * D_ + _kof + _qu * 8;             \
        }                                                                     \
        asm volatile("cp.async.cg.shared.global [%0], [%1], 16;"              \
                     :: "r"(_dst), "l"(_sp));                                 \
    }                                                                         \
    asm volatile("cp.async.commit_group;" ::: "memory");                      \
} while (0)

    ISSUE(0, 0);
    ISSUE(1, 1);

    int st = 0;
    for (int ch = 0; ch < NCH; ch++) {
        if (ch < NCH - 1) asm volatile("cp.async.wait_group 1;" ::: "memory");
        else              asm volatile("cp.async.wait_group 0;" ::: "memory");
        __syncthreads();
        {
            int nst = st + 2; if (nst >= NSTAGE) nst -= NSTAGE;
            if (ch + 2 < NCH) ISSUE(ch + 2, nst);
        }

        const uint32_t stb = sm0 + st * STAGEB;
        const uint32_t aHi = stb + OFF_XHI + (wy * 32 + lrow) * ROWB + colh;
        const uint32_t bHi = stb + OFF_WHI + (wx * 32 + lrow) * ROWB + colh;

        #pragma unroll
        for (int ks = 0; ks < 2; ks++) {
            uint32_t ah[2][4], al[2][4], bh[2][4], bl[2][4];
            #pragma unroll
            for (int mb = 0; mb < 2; mb++) {
                LDSM4(ah[mb], aHi + mb * 16 * ROWB + ks * 32);
                LDSM4(al[mb], aHi + TILEA + mb * 16 * ROWB + ks * 32);
            }
            #pragma unroll
            for (int t2 = 0; t2 < 2; t2++) {
                LDSM4(bh[t2], bHi + t2 * 16 * ROWB + ks * 32);
                LDSM4(bl[t2], bHi + TILEW + t2 * 16 * ROWB + ks * 32);
            }
            // Term-major issue: 8 independent MMAs per term
            #pragma unroll
            for (int t2 = 0; t2 < 2; t2++)
                #pragma unroll
                for (int mb = 0; mb < 2; mb++) {
                    MMA16816(acc[mb][t2 * 2],     ah[mb][0], ah[mb][1], ah[mb][2], ah[mb][3], bh[t2][0], bh[t2][2]);
                    MMA16816(acc[mb][t2 * 2 + 1], ah[mb][0], ah[mb][1], ah[mb][2], ah[mb][3], bh[t2][1], bh[t2][3]);
                }
            #pragma unroll
            for (int t2 = 0; t2 < 2; t2++)
                #pragma unroll
                for (int mb = 0; mb < 2; mb++) {
                    MMA16816(acc[mb][t2 * 2],     ah[mb][0], ah[mb][1], ah[mb][2], ah[mb][3], bl[t2][0], bl[t2][2]);
                    MMA16816(acc[mb][t2 * 2 + 1], ah[mb][0], ah[mb][1], ah[mb][2], ah[mb][3], bl[t2][1], bl[t2][3]);
                }
            #pragma unroll
            for (int t2 = 0; t2 < 2; t2++)
                #pragma unroll
                for (int mb = 0; mb < 2; mb++) {
                    MMA16816(acc[mb][t2 * 2],     al[mb][0], al[mb][1], al[mb][2], al[mb][3], bh[t2][0], bh[t2][2]);
                    MMA16816(acc[mb][t2 * 2 + 1], al[mb][0], al[mb][1], al[mb][2], al[mb][3], bh[t2][1], bh[t2][3]);
                }
        }
        st = st + 1 >= NSTAGE ? 0 : st + 1;
        // next iteration's __syncthreads protects stage reuse
    }
#undef ISSUE

    // Epilogue
    if (gate_mode == 0) {
        #pragma unroll
        for (int mb = 0; mb < 2; mb++) {
            const int m0 = bm + wy * 32 + mb * 16 + g;
            #pragma unroll
            for (int j = 0; j < 4; j++) {
                const int n0 = bn + wx * 32 + j * 8 + 2 * q;
                const float d0 = bias[n0], d1 = bias[n0 + 1];
                *(float2*)(C + (size_t)m0 * G_ + n0) =
                    make_float2(acc[mb][j][0] + d0, acc[mb][j][1] + d1);
                *(float2*)(C + (size_t)(m0 + 8) * G_ + n0) =
                    make_float2(acc[mb][j][2] + d0, acc[mb][j][3] + d1);
            }
        }
        return;
    }

    // gate_mode == 1: fused LSTM cell update (writes ping-pong OUT buffers)
    const int evn = (lane & 1) == 0;   // q even: holds (i,f); q odd: (g,o)
    #pragma unroll
    for (int mb = 0; mb < 2; mb++) {
        const int r0 = bm + wy * 32 + mb * 16 + g;
        #pragma unroll
        for (int j = 0; j < 4; j++) {
            const int n0 = bn + wx * 32 + j * 8 + 2 * q;
            const float2 p0 = *(const float2*)(xg + (size_t)r0 * G_ + n0);
            const float2 p1 = *(const float2*)(xg + (size_t)(r0 + 8) * G_ + n0);
            float v0 = acc[mb][j][0] + p0.x;
            float v1 = acc[mb][j][1] + p0.y;
            float v2 = acc[mb][j][2] + p1.x;
            float v3 = acc[mb][j][3] + p1.y;

            const float s0 = __shfl_xor_sync(0xffffffffu, v0, 1);
            const float s1 = __shfl_xor_sync(0xffffffffu, v1, 1);
            const float s2 = __shfl_xor_sync(0xffffffffu, v2, 1);
            const float s3 = __shfl_xor_sync(0xffffffffu, v3, 1);

            // even lane handles row r0; odd lane handles row r0+8
            const int   row = evn ? r0 : r0 + 8;
            const float gi = evn ? v0 : s2;
            const float gf = evn ? v1 : s3;
            const float gg = evn ? s0 : v2;
            const float go = evn ? s1 : v3;

            const float iv = 1.f / (1.f + expf(-gi));
            const float fv = 1.f / (1.f + expf(-gf));
            const float gv = tanhf(gg);
            const float ov = 1.f / (1.f + expf(-go));

            const int  u   = (n0 >> 2);               // original hidden unit
            const int  idx = row * H_ + u;
            const float cn = fv * c[idx] + iv * gv;
            c[idx] = cn;
            const float hv = ov * tanhf(cn);
            h[idx] = hv;
            const __nv_bfloat16 hb = __float2bfloat16(hv);
            hhi_out[idx] = hb;
            hlo_out[idx] = __float2bfloat16(hv - __bfloat162float(hb));
        }
    }
}

// ---------------------------------------------------------------------------
// Fused prep: wih decomp (permuted) + whh decomp (permuted) + x decomp + bias
// ---------------------------------------------------------------------------
#define NW (G_ * D_)
__global__ void prep_kernel(const float* __restrict__ x,
                            const float* __restrict__ Wih,
                            const float* __restrict__ Whh,
                            const float* __restrict__ bih,
                            const float* __restrict__ bhh,
                            __nv_bfloat16* __restrict__ wih_hi,
                            __nv_bfloat16* __restrict__ wih_lo,
                            __nv_bfloat16* __restrict__ whh_hi,
                            __nv_bfloat16* __restrict__ whh_lo,
                            __nv_bfloat16* __restrict__ x_hi,
                            __nv_bfloat16* __restrict__ x_lo,
                            float* __restrict__ bias)
{
    const long long i = (long long)blockIdx.x * blockDim.x + threadIdx.x;
    if (i < NW) {
        const int p   = (int)(i / D_);
        const int col = (int)(i - (long long)p * D_);
        const int srow = (p & 3) * H_ + (p >> 2);
        const float v = Wih[(size_t)srow * D_ + col];
        const __nv_bfloat16 hb = __float2bfloat16(v);
        wih_hi[i] = hb;
        wih_lo[i] = __float2bfloat16(v - __bfloat162float(hb));
    } else if (i < 2LL * NW) {
        const long long j = i - NW;
        const int p   = (int)(j / H_);
        const int col = (int)(j - (long long)p * H_);
        const int srow = (p & 3) * H_ + (p >> 2);
        const float v = Whh[(size_t)srow * H_ + col];
        const __nv_bfloat16 hb = __float2bfloat16(v);
        whh_hi[j] = hb;
        whh_lo[j] = __float2bfloat16(v - __bfloat162float(hb));
    } else if (i < 2LL * NW + B_ * D_) {
        const int j = (int)(i - 2LL * NW);
        const float v = x[j];
        const __nv_bfloat16 hb = __float2bfloat16(v);
        x_hi[j] = hb;
        x_lo[j] = __float2bfloat16(v - __bfloat162float(hb));
    } else if (i < 2LL * NW + B_ * D_ + G_) {
        const int p = (int)(i - 2LL * NW - B_ * D_);
        const int o = (p & 3) * H_ + (p >> 2);
        bias[p] = bih[o] + bhh[o];
    }
}

// ---------------------------------------------------------------------------
// t=0 gate: g = xg (h0 = 0), permuted layout
// ---------------------------------------------------------------------------
__global__ void gate0_kernel(const float* __restrict__ xg,
                             float* __restrict__ h,
                             float* __restrict__ c,
                             __nv_bfloat16* __restrict__ hhi,
                             __nv_bfloat16* __restrict__ hlo)
{
    const int idx = blockIdx.x * blockDim.x + threadIdx.x;
    if (idx >= B_ * H_) return;
    const int b = idx / H_;
    const int u = idx - b * H_;
    const float* gr = xg + (size_t)b * G_ + 4 * u;

    const float iv = 1.f / (1.f + expf(-gr[0]));
    const float gv = tanhf(gr[2]);
    const float ov = 1.f / (1.f + expf(-gr[3]));

    const float cn = iv * gv;          // c0 = 0
    c[idx] = cn;
    const float hv = ov * tanhf(cn);
    h[idx] = hv;
    const __nv_bfloat16 hb = __float2bfloat16(hv);
    hhi[idx] = hb;
    hlo[idx] = __float2bfloat16(hv - __bfloat162float(hb));
}

// ---------------------------------------------------------------------------
// fe GEMM, split-K: part[s][m][n] = sum_{k in chunk s} h[m,k] * W_fe[n,k]
// ---------------------------------------------------------------------------
__global__ __launch_bounds__(256, 1)
void gemm_fe(const float* __restrict__ hmat,
             const float* __restrict__ Wfe,
             float* __restrict__ part)
{
    __shared__ float As[16][68];
    __shared__ float Bs[16][132];

    const int ks   = blockIdx.x;
    const int bm   = blockIdx.y * 64;
    const int koff = ks * KC;
    const int tid  = threadIdx.x;
    const int tx   = tid & 31;
    const int ty   = tid >> 5;

    float acc[8][4];
    #pragma unroll
    for (int i = 0; i < 8; i++)
        #pragma unroll
        for (int j = 0; j < 4; j++) acc[i][j] = 0.f;

    for (int k0 = 0; k0 < KC; k0 += 16) {
        {
            const int row = tid >> 2;
            const int c4  = (tid & 3) * 4;
            float4 v = *(const float4*)(hmat + (size_t)(bm + row) * H_ + koff + k0 + c4);
            As[c4 + 0][row] = v.x;  As[c4 + 1][row] = v.y;
            As[c4 + 2][row] = v.z;  As[c4 + 3][row] = v.w;
        }
        #pragma unroll
        for (int r = 0; r < 2; r++) {
            const int idx = tid + r * 256;
            const int rowb = idx >> 2;
            const int c4  = (idx & 3) * 4;
            float4 v = *(const float4*)(Wfe + (size_t)rowb * H_ + koff + k0 + c4);
            Bs[c4 + 0][rowb] = v.x;  Bs[c4 + 1][rowb] = v.y;
            Bs[c4 + 2][rowb] = v.z;  Bs[c4 + 3][rowb] = v.w;
        }
        __syncthreads();

        #pragma unroll
        for (int kk = 0; kk < 16; kk++) {
            float a[8], b[4];
            #pragma unroll
            for (int i = 0; i < 8; i++) a[i] = As[kk][ty + i * 8];
            #pragma unroll
            for (int j = 0; j < 4; j++) b[j] = Bs[kk][tx + j * 32];
            #pragma unroll
            for (int i = 0; i < 8; i++)
                #pragma unroll
                for (int j = 0; j < 4; j++)
                    acc[i][j] = fmaf(a[i], b[j], acc[i][j]);
        }
        __syncthreads();
    }

    #pragma unroll
    for (int i = 0; i < 8; i++) {
        const int m = bm + ty + i * 8;
        #pragma unroll
        for (int j = 0; j < 4; j++) {
            const int n = tx + j * 32;
            part[((size_t)ks * B_ + m) * (2 * K_) + n] = acc[i][j];
        }
    }
}

// ---------------------------------------------------------------------------
// z epilogue
// ---------------------------------------------------------------------------
__global__ void z_kernel(const float* __restrict__ eps,
                         const float* __restrict__ bfe,
                         const float* __restrict__ part,
                         float* __restrict__ out,
                         int t)
{
    const int idx = blockIdx.x * blockDim.x + threadIdx.x;
    if (idx >= B_ * K_) return;
    const int b = idx / K_;
    const int k = idx - b * K_;

    float mu = bfe[k];
    float sr = bfe[k + K_];
    #pragma unroll
    for (int s = 0; s < NS; s++) {
        const float* p = part + ((size_t)s * B_ + b) * (2 * K_);
        mu += p[k];
        sr += p[k + K_];
    }

    const float xv  = sr - 5.f;
    const float sig = (xv > 20.f) ? xv : log1pf(expf(xv));
    const float e   = eps[((size_t)t * B_ + b) * K_ + k];
    const float z   = e * sig + mu;

    const size_t plane = (size_t)B_ * K_ * T_;
    const size_t o = ((size_t)b * K_ + k) * T_ + t;
    out[o]             = z;
    out[o + plane]     = mu;
    out[o + 2 * plane] = sig;
}

__global__ void hc_copy(const float* __restrict__ h,
                        const float* __restrict__ c,
                        float* __restrict__ out)
{
    const int idx = blockIdx.x * blockDim.x + threadIdx.x;
    if (idx >= B_ * H_) return;
    const size_t base = 3 * (size_t)B_ * K_ * T_;
    out[base + idx]           = h[idx];
    out[base + B_ * H_ + idx] = c[idx];
}

// ---------------------------------------------------------------------------
extern "C" void kernel_launch(void* const* d_in, const int* in_sizes, int n_in,
                              void* d_out, int out_size)
{
    const float* x   = (const float*)d_in[0];
    const float* eps = (const float*)d_in[1];
    const float* Wih = (const float*)d_in[2];
    const float* Whh = (const float*)d_in[3];
    const float* bih = (const float*)d_in[4];
    const float* bhh = (const float*)d_in[5];
    const float* Wfe = (const float*)d_in[6];
    const float* bfe = (const float*)d_in[7];
    float* out = (float*)d_out;

    __nv_bfloat16 *wih_hi, *wih_lo, *whh_hi, *whh_lo, *x_hi, *x_lo, *hhi2, *hlo2;
    float *xg, *h, *c, *fep, *bias;
    cudaGetSymbolAddress((void**)&wih_hi, d_wih_hi);
    cudaGetSymbolAddress((void**)&wih_lo, d_wih_lo);
    cudaGetSymbolAddress((void**)&whh_hi, d_whh_hi);
    cudaGetSymbolAddress((void**)&whh_lo, d_whh_lo);
    cudaGetSymbolAddress((void**)&x_hi,   d_x_hi);
    cudaGetSymbolAddress((void**)&x_lo,   d_x_lo);
    cudaGetSymbolAddress((void**)&hhi2,   d_h_hi);
    cudaGetSymbolAddress((void**)&hlo2,   d_h_lo);
    cudaGetSymbolAddress((void**)&xg,   d_xg);
    cudaGetSymbolAddress((void**)&h,    d_h);
    cudaGetSymbolAddress((void**)&c,    d_c);
    cudaGetSymbolAddress((void**)&fep,  d_fep);
    cudaGetSymbolAddress((void**)&bias, d_bias);

    __nv_bfloat16* hhi_buf[2] = { hhi2, hhi2 + B_ * H_ };
    __nv_bfloat16* hlo_buf[2] = { hlo2, hlo2 + B_ * H_ };

    cudaFuncSetAttribute(gemm_mma2, cudaFuncAttributeMaxDynamicSharedMemorySize,
                         SMEM_TOTAL);

    const dim3 gTc(G_ / 128, B_ / 64);     // (64, 4) = 256 CTAs
    const dim3 gFe(NS, B_ / 64);           // (32, 4)
    const int  eltBlocks = (B_ * H_ + 255) / 256;
    const int  zBlocks   = (B_ * K_ + 255) / 256;

    // Fused prep (single launch)
    const long long prepN = 2LL * NW + B_ * D_ + G_;
    prep_kernel<<<(int)((prepN + 255) / 256), 256>>>(
        x, Wih, Whh, bih, bhh,
        wih_hi, wih_lo, whh_hi, whh_lo, x_hi, x_lo, bias);

    // xg = x @ Wih_perm^T + bias_perm   (permuted cols)
    gemm_mma2<<<gTc, 256, SMEM_TOTAL>>>(x_hi, x_lo, wih_hi, wih_lo,
                                        nullptr, bias, xg,
                                        nullptr, nullptr, nullptr, nullptr, 0);

    for (int t = 0; t < T_; t++) {
        if (t == 0) {
            gate0_kernel<<<eltBlocks, 256>>>(xg, h, c, hhi_buf[0], hlo_buf[0]);
        } else {
            // read tick (t-1)'s h from buf[(t-1)&1], write tick t's h to buf[t&1]
            gemm_mma2<<<gTc, 256, SMEM_TOTAL>>>(hhi_buf[(t - 1) & 1], hlo_buf[(t - 1) & 1],
                                                whh_hi, whh_lo,
                                                xg, nullptr, nullptr,
                                                h, c, hhi_buf[t & 1], hlo_buf[t & 1], 1);
        }
        gemm_fe<<<gFe, 256>>>(h, Wfe, fep);
        z_kernel<<<zBlocks, 256>>>(eps, bfe, fep, out, t);
    }

    hc_copy<<<eltBlocks, 256>>>(h, c, out);
}